// round 17
// baseline (speedup 1.0000x reference)
#include <cuda_runtime.h>
#include <cstdint>

// ConvTranspose2d(64->64,k4,s2,p1)+bias+mish+(+0.5,clip,*2) via mma.sync fp16 (f32 accum).
// y[p,oc] = sum_k A[p,k]*B[oc,k], k = (b*2+a)*64 + ic, K=256.
//   tile = ONE output q-row: oh = 2*Rb - ph, ow = 2m+pw (m=0..63); Rb = q + ph
//   A[p,k] = x[n, ic, Rb-a, m+pw-b]  (zero OOB), B[oc,k]=w[oc,ic,(1-ph)+2a,(1-pw)+2b]
// == Round-11 mainloop/epilogue per warp, but CTA halved to 256 thr / 8 warps
// = (pw, och, mq2), tile 64px x 64oc x 2pw -> SMEM 106.9KB -> 2 CTAs/SM with
// INDEPENDENT barrier domains (phases of the two CTAs interleave on the SM).
// No staging duplication (CTAs own disjoint work units).
// 3-slot fp16 row ring (slot=rg%3, row 128B = 64 ic, 16B-chunk swizzle ^(j&7)<<4,
// OOB j -> ZROW). Staging: LDG.32 ic-pair -> cvt.rn.f16x2 -> STS.32.
// Unit = 8 q-rows (512 units/ph, 148 slots). Grid 296.
// Epilogue: 2x8KB ys, 4 chunks x 16oc, store(q) overlaps write(q+1).

#define NT 256
#define SM_B    256
#define SM_RING (SM_B + 65536)             // 65792
#define ZROW    192
#define SM_YS   (SM_RING + 193 * 128)      // 90496
#define SMEM_TOTAL (SM_YS + 16384)         // 106880

static __device__ __forceinline__ uint32_t s2u(const void* p) {
    uint32_t a;
    asm("{ .reg .u64 t; cvta.to.shared.u64 t, %1; cvt.u32.u64 %0, t; }" : "=r"(a) : "l"(p));
    return a;
}
static __device__ __forceinline__ uint32_t f2h2(float lo, float hi) {
    uint32_t r;
    asm("cvt.rn.f16x2.f32 %0, %1, %2;" : "=r"(r) : "f"(hi), "f"(lo));
    return r;
}
static __device__ __forceinline__ void sts32(uint32_t addr, uint32_t v) {
    asm volatile("st.shared.b32 [%0], %1;" :: "r"(addr), "r"(v) : "memory");
}
static __device__ __forceinline__ void ldsm4(uint32_t* r, uint32_t addr) {
    asm volatile("ldmatrix.sync.aligned.m8n8.x4.shared.b16 {%0,%1,%2,%3}, [%4];"
                 : "=r"(r[0]), "=r"(r[1]), "=r"(r[2]), "=r"(r[3]) : "r"(addr));
}
static __device__ __forceinline__ void mma16(float* d, const uint32_t* a,
                                             uint32_t b0, uint32_t b1) {
    asm volatile("mma.sync.aligned.m16n8k16.row.col.f32.f16.f16.f32 "
                 "{%0,%1,%2,%3}, {%4,%5,%6,%7}, {%8,%9}, {%0,%1,%2,%3};"
                 : "+f"(d[0]), "+f"(d[1]), "+f"(d[2]), "+f"(d[3])
                 : "r"(a[0]), "r"(a[1]), "r"(a[2]), "r"(a[3]), "r"(b0), "r"(b1));
}
__device__ __forceinline__ float postop(float y) {
    // mish(y) = y*(t^2+2t)/(t^2+2t+2), t=e^y ; then +0.5, clip[-1,1], *2
    float t = __expf(fminf(y, 30.0f));
    float u = t * (t + 2.0f);
    float mish = y * __fdividef(u, u + 2.0f);
    float v = fminf(fmaxf(mish + 0.5f, -1.0f), 1.0f);
    return v * 2.0f;
}
// ys: 32 rows x 256B (64 px), 16B-chunk XOR swizzle by (row&15)
static __device__ __forceinline__ uint32_t ysaddr(uint32_t base, int row, int p) {
    return base + (uint32_t)row * 256 + ((((uint32_t)p >> 2) ^ (uint32_t)(row & 15)) << 4)
         + (((uint32_t)p & 3) << 2);
}

// stage nrows rows starting at rg0: LDG.32 ic-pair -> f16x2 -> STS.32 ; slot = rg%3
static __device__ __forceinline__ void stage_rows(const float* xn, int rg0, int nrows,
                                                  uint32_t sb, int tid) {
    const int total = nrows * 2048;        // pairs: 32 icp x 64 j per row
#pragma unroll 4
    for (int idx = tid; idx < total; idx += NT) {
        int j   = idx & 63;
        int icp = (idx >> 6) & 31;
        int rr  = idx >> 11;
        int rg  = rg0 + rr;
        float v0 = 0.0f, v1 = 0.0f;
        if ((unsigned)rg < 64u) {
            const float* p0 = xn + ((2 * icp) * 64 + rg) * 64 + j;
            v0 = __ldg(p0);
            v1 = __ldg(p0 + 4096);
        }
        int row = ((rg + 3) % 3) * 64 + j;
        uint32_t dst = sb + SM_RING + row * 128
                     + (((uint32_t)icp << 2) ^ (((uint32_t)j & 7) << 4));
        sts32(dst, f2h2(v0, v1));
    }
}

__global__ __launch_bounds__(NT, 2)
void convt_mma_kernel(const float* __restrict__ x,
                      const float* __restrict__ weight,
                      const float* __restrict__ bias,
                      float* __restrict__ out) {
    extern __shared__ char smem[];
    const uint32_t sb = s2u(smem);
    const int tid  = threadIdx.x;
    const int warp = tid >> 5;
    const int lane = tid & 31;
    const int ph   = blockIdx.x & 1;
    const int sct  = blockIdx.x >> 1;      // 0..147

    if (tid < 64) ((float*)smem)[tid] = bias[tid];

    // ---- stage B once (fp16): row = pw*64+oc (512B), word kp: byte = kp*4 ^ ((oc&7)<<4) ----
    for (int it = 0; it < 64; it++) {
        int idx = tid + it * NT;           // 0..16383 (k-pairs)
        int kp = idx & 127;                // k0 = 2*kp
        int oc = (idx >> 7) & 63;
        int pw = idx >> 13;
        int k0 = 2 * kp;
        int g = k0 >> 6, ic = k0 & 63, a = g & 1, b = g >> 1;
        int kh = (1 - ph) + 2 * a;
        int kw = (1 - pw) + 2 * b;
        const float* wp = weight + ((oc * 64 + ic) << 4) + (kh << 2) + kw;
        float f0 = __ldg(wp);
        float f1 = __ldg(wp + 16);         // ic+1, same (kh,kw)
        uint32_t byte = ((uint32_t)(kp << 2)) ^ ((uint32_t)(oc & 7) << 4);
        sts32(sb + SM_B + (pw * 64 + oc) * 512 + byte, f2h2(f0, f1));
    }
    if (tid < 32) sts32(sb + SM_RING + ZROW * 128 + tid * 4, 0u);   // zero row

    // warp roles: pw | och | mq  (8 warps)
    const int pw  = warp >> 2;
    const int och = (warp >> 1) & 1;
    const int mq  = warp & 1;
    const int p0  = 32 * mq;               // m base
    const int msub0 = 32 * mq;

    const int l15 = lane & 15;
    const int lhi = lane >> 4;
    const int oc_l = (lane & 7) + 8 * lhi;
    const uint32_t khalf = (uint32_t)((lane >> 3) & 1) << 4;
    const uint32_t swzB  = (uint32_t)(lane & 7) << 4;
    uint32_t rbB[2];
#pragma unroll
    for (int jp = 0; jp < 2; jp++)
        rbB[jp] = sb + SM_B + (uint32_t)(pw * 64 + 32 * och + 16 * jp + oc_l) * 512;

    const int gL = lane >> 2, tg = lane & 3;
    const float* bsm = (const float*)smem;

    for (int u = sct; u < 512; u += 148) {
        const int n  = u >> 3;
        const int uh = u & 7;
        const int Rb0 = 8 * uh + ph;
        const float* xn = x + (size_t)n * (64 * 64 * 64);

        // ---- prologue: rows Rb0-1, Rb0 ----
        stage_rows(xn, Rb0 - 1, 2, sb, tid);
        __syncthreads();

        for (int tl = 0; tl < 8; tl++) {
            const int Rb = Rb0 + tl;       // tile q-row: oh = 2*Rb - ph

            // ---- phase A: stage row Rb+1 (next tile) ----
            if (tl < 7) stage_rows(xn, Rb + 1, 1, sb, tid);

            // ---- phase B: mma from slots (Rb-1, Rb), 16 k16-steps ----
            float acc[2][4][4];
#pragma unroll
            for (int i = 0; i < 2; i++)
#pragma unroll
                for (int j = 0; j < 4; j++)
#pragma unroll
                    for (int e = 0; e < 4; e++) acc[i][j][e] = 0.0f;

#pragma unroll
            for (int g = 0; g < 4; g++) {
                const int a = g & 1, b = g >> 1;
                const int rgA = Rb - a;
                const int slotA = (rgA + 3) % 3;
                const int jA = msub0 + pw - b + l15;
                const int rowL0 = ((unsigned)jA < 64u) ? slotA * 64 + jA : ZROW;
                const int rowL1 = ((unsigned)(jA + 16) < 64u) ? slotA * 64 + jA + 16 : ZROW;
                const uint32_t base0 = sb + SM_RING + (uint32_t)rowL0 * 128;
                const uint32_t base1 = sb + SM_RING + (uint32_t)rowL1 * 128;
                const uint32_t r0 = (uint32_t)(rowL0 & 7);
                const uint32_t r1 = (uint32_t)(rowL1 & 7);
                const uint32_t kbg = (uint32_t)g << 7;   // g*128 bytes

#pragma unroll
                for (int s = 0; s < 4; s++) {
                    const uint32_t ch = (uint32_t)(s << 1) + (uint32_t)lhi;  // 0..7
                    uint32_t Af0[4], Af1[4];
                    ldsm4(Af0, base0 + ((ch ^ r0) << 4));
                    ldsm4(Af1, base1 + ((ch ^ r1) << 4));
                    const uint32_t kb = (kbg + ((uint32_t)s << 5) + khalf) ^ swzB;
                    uint32_t Bf0[4], Bf1[4];
                    ldsm4(Bf0, rbB[0] + kb);
                    ldsm4(Bf1, rbB[1] + kb);
                    mma16(acc[0][0], Af0, Bf0[0], Bf0[1]);
                    mma16(acc[0][1], Af0, Bf0[2], Bf0[3]);
                    mma16(acc[0][2], Af0, Bf1[0], Bf1[1]);
                    mma16(acc[0][3], Af0, Bf1[2], Bf1[3]);
                    mma16(acc[1][0], Af1, Bf0[0], Bf0[1]);
                    mma16(acc[1][1], Af1, Bf0[2], Bf0[3]);
                    mma16(acc[1][2], Af1, Bf1[0], Bf1[1]);
                    mma16(acc[1][3], Af1, Bf1[2], Bf1[3]);
                }
            }
            __syncthreads();   // sync1: ring reads done; phase-A STS visible next tile

            // ---- phase C: ys 2x8KB double buffer, 4 chunks x 16oc ----
            const uint32_t ysA = sb + SM_YS;
            const uint32_t ysB = sb + SM_YS + 8192;
            const int rowc = pw * 16 + 8 * och + 2 * tg;
            const int oh = 2 * Rb - ph;

#define WRITE_CHUNK(q, base) do {                                            \
    const int occ_ = 32 * och + 8 * (q) + 2 * tg;                            \
    const float b0v_ = bsm[occ_], b1v_ = bsm[occ_ + 1];                      \
    _Pragma("unroll")                                                        \
    for (int i_ = 0; i_ < 2; i_++) {                                         \
        const int pr_ = p0 + 16 * i_ + gL;                                   \
        sts32(ysaddr((base), rowc,     pr_),     __float_as_uint(postop(acc[i_][q][0] + b0v_))); \
        sts32(ysaddr((base), rowc + 1, pr_),     __float_as_uint(postop(acc[i_][q][1] + b1v_))); \
        sts32(ysaddr((base), rowc,     pr_ + 8), __float_as_uint(postop(acc[i_][q][2] + b0v_))); \
        sts32(ysaddr((base), rowc + 1, pr_ + 8), __float_as_uint(postop(acc[i_][q][3] + b1v_))); \
    } } while (0)

#define STORE_CHUNK(q, base) do {                                            \
    const char* yb_ = smem + ((base) - sb);                                  \
    _Pragma("unroll")                                                        \
    for (int it_ = 0; it_ < 2; it_++) {                                      \
        int vid_ = tid + it_ * NT;     /* 0..511 */                          \
        int ow4_ = vid_ & 31;                                                \
        int ocx_ = vid_ >> 5;          /* 0..15 */                           \
        int oc_  = 32 * (ocx_ >> 3) + 8 * (q) + (ocx_ & 7);                  \
        int p_   = 2 * ow4_;                                                 \
        float4 v_;                                                           \
        v_.x = *(const float*)(yb_ + (ysaddr(0u, ocx_,      p_)));           \
        v_.y = *(const float*)(yb_ + (ysaddr(0u, 16 + ocx_, p_)));           \
        v_.z = *(const float*)(yb_ + (ysaddr(0u, ocx_,      p_ + 1)));       \
        v_.w = *(const float*)(yb_ + (ysaddr(0u, 16 + ocx_, p_ + 1)));       \
        *(float4*)(out + (((size_t)n * 64 + oc_) * 128 + oh) * 128 + 4 * ow4_) = v_; \
    } } while (0)

            WRITE_CHUNK(0, ysA);
            __syncthreads();
            STORE_CHUNK(0, ysA); WRITE_CHUNK(1, ysB);
            __syncthreads();
            STORE_CHUNK(1, ysB); WRITE_CHUNK(2, ysA);
            __syncthreads();
            STORE_CHUNK(2, ysA); WRITE_CHUNK(3, ysB);
            __syncthreads();
            STORE_CHUNK(3, ysB);
            __syncthreads();
#undef WRITE_CHUNK
#undef STORE_CHUNK
        }
    }
}

extern "C" void kernel_launch(void* const* d_in, const int* in_sizes, int n_in,
                              void* d_out, int out_size) {
    const float* x      = (const float*)d_in[0];
    const float* weight = (const float*)d_in[1];
    const float* bias   = (const float*)d_in[2];
    float* out          = (float*)d_out;

    cudaFuncSetAttribute(convt_mma_kernel,
                         cudaFuncAttributeMaxDynamicSharedMemorySize, SMEM_TOTAL);
    convt_mma_kernel<<<296, NT, SMEM_TOTAL>>>(x, weight, bias, out);
}